// round 4
// baseline (speedup 1.0000x reference)
#include <cuda_runtime.h>
#include <math.h>

#define BATCH 16
#define NN    2048
#define KH    12
#define FD    128
#define OD    64

// attention scratch: att[2][NN][6][6]
__device__ float g_att[2 * NN * 36];

typedef unsigned long long u64;

__device__ __forceinline__ void fma2(u64& acc, u64 a, u64 b) {
    asm("fma.rn.f32x2 %0, %1, %2, %0;" : "+l"(acc) : "l"(a), "l"(b));
}
__device__ __forceinline__ float hadd2(u64 v) {
    float2 f;
    asm("mov.b64 {%0, %1}, %2;" : "=f"(f.x), "=f"(f.y) : "l"(v));
    return f.x + f.y;
}

// ---------------------------------------------------------------------------
// Kernel A: attention matrices. One warp per (i, n). 1024 blocks x 128 thr.
// ---------------------------------------------------------------------------
__global__ void __launch_bounds__(128) attn_scores_kernel(
    const float* __restrict__ h, const int* __restrict__ adj,
    const float* __restrict__ W, const float* __restrict__ a)
{
    __shared__ float wa1[FD], wa2[FD];
    const int t = threadIdx.x;
    const int i = blockIdx.x >> 9;               // 1024 blocks: 512 per i

    {   // all 128 threads: wa = W @ a1 / a2
        float r1 = 0.f, r2 = 0.f;
        const float* wr = W + t * OD;
        const float* ap = a + i * 2 * OD;
        #pragma unroll 16
        for (int o = 0; o < OD; ++o) {
            const float w = wr[o];
            r1 = fmaf(w, ap[o], r1);
            r2 = fmaf(w, ap[OD + o], r2);
        }
        wa1[t] = r1; wa2[t] = r2;
    }
    __syncthreads();

    const int wid = t >> 5, l = t & 31;
    const int n = ((blockIdx.x & 511) << 2) + wid;

    float p1[6], p2[6];
    const float* hb = h + (((size_t)i * NN + n) * KH + i * 6) * FD;
    #pragma unroll
    for (int q = 0; q < 6; ++q) { p1[q] = 0.f; p2[q] = 0.f; }
    #pragma unroll
    for (int it = 0; it < 4; ++it) {
        const int f = l + it * 32;
        const float w1 = wa1[f], w2 = wa2[f];
        #pragma unroll
        for (int q = 0; q < 6; ++q) {
            const float hv = hb[q * FD + f];
            p1[q] = fmaf(hv, w1, p1[q]);
            p2[q] = fmaf(hv, w2, p2[q]);
        }
    }
    #pragma unroll
    for (int off = 16; off > 0; off >>= 1) {
        #pragma unroll
        for (int q = 0; q < 6; ++q) {
            p1[q] += __shfl_xor_sync(0xffffffffu, p1[q], off);
            p2[q] += __shfl_xor_sync(0xffffffffu, p2[q], off);
        }
    }

    if (l < 6) {
        const int p = l;
        float e[6];
        float m = -1e30f;
        #pragma unroll
        for (int q = 0; q < 6; ++q) {
            float v = p1[p] + p2[q];
            v = v > 0.f ? v : 0.2f * v;
            if (adj[i * 36 + p * 6 + q] <= 0) v = -9.0e15f;
            e[q] = v;
            m = fmaxf(m, v);
        }
        float sum = 0.f;
        #pragma unroll
        for (int q = 0; q < 6; ++q) { e[q] = expf(e[q] - m); sum += e[q]; }
        const float inv = 1.f / sum;
        float* dst = g_att + ((size_t)i * NN + n) * 36 + p * 6;
        #pragma unroll
        for (int q = 0; q < 6; ++q) dst[q] = e[q] * inv;
    }
}

// ---------------------------------------------------------------------------
// Kernel B: out = elu( postmix( h @ W ) )
// f-pair FFMA2: acc[q][c] accumulates (even-f, odd-f) partial sums.
//   A operand  : LDG.128 of h (16-lane broadcast, no smem, no splat)
//   W operand  : LDS.128 from transposed smem WtG[f4][c4][cg] (conflict-free)
// Warp job = one n (both k-groups via lane halves). 4 jobs per warp.
// ---------------------------------------------------------------------------
#define THREADS 128

// WtG granule (f4, c4, cg) = { W[4f4+k][cg*4+c4] : k=0..3 } as 2 u64 f-pairs
__global__ void __launch_bounds__(THREADS, 4) gat_main_kernel(
    const float* __restrict__ h, const float* __restrict__ W,
    float* __restrict__ out)
{
    __shared__ float4 WtG[2048];          // 32 KB
    const int t = threadIdx.x;

    // one-time transposed fill
    for (int gidx = t; gidx < 2048; gidx += THREADS) {
        const int f4 = gidx >> 6;
        const int c4 = (gidx >> 4) & 3;
        const int cg = gidx & 15;
        const int c  = cg * 4 + c4;
        float4 v;
        v.x = W[(f4 * 4 + 0) * OD + c];
        v.y = W[(f4 * 4 + 1) * OD + c];
        v.z = W[(f4 * 4 + 2) * OD + c];
        v.w = W[(f4 * 4 + 3) * OD + c];
        WtG[gidx] = v;
    }
    __syncthreads();

    const int w    = t >> 5;
    const int lane = t & 31;
    const int gl   = lane >> 4;       // k-group 0/1
    const int cg   = lane & 15;       // output cols cg*4..cg*4+3
    const int b    = blockIdx.y;
    const int n0   = blockIdx.x * 16;

    const ulonglong2* Wg = (const ulonglong2*)WtG;

    for (int it = 0; it < 4; ++it) {
        const int n = n0 + w * 4 + it;
        const ulonglong2* hb = (const ulonglong2*)
            (h + (((size_t)b * NN + n) * KH + gl * 6) * FD);

        u64 acc[6][4];
        #pragma unroll
        for (int q = 0; q < 6; ++q)
            #pragma unroll
            for (int c = 0; c < 4; ++c) acc[q][c] = 0ull;

        #pragma unroll 4
        for (int f4 = 0; f4 < 32; ++f4) {
            ulonglong2 av[6];
            #pragma unroll
            for (int q = 0; q < 6; ++q)
                av[q] = hb[q * 32 + f4];           // LDG.128 broadcast
            ulonglong2 wv[4];
            #pragma unroll
            for (int c = 0; c < 4; ++c)
                wv[c] = Wg[f4 * 64 + c * 16 + cg]; // LDS.128 contiguous
            #pragma unroll
            for (int q = 0; q < 6; ++q) {
                #pragma unroll
                for (int c = 0; c < 4; ++c) {
                    fma2(acc[q][c], av[q].x, wv[c].x);
                    fma2(acc[q][c], av[q].y, wv[c].y);
                }
            }
        }

        // horizontal add -> scalar Wh values
        float s[6][4];
        #pragma unroll
        for (int q = 0; q < 6; ++q)
            #pragma unroll
            for (int c = 0; c < 4; ++c) s[q][c] = hadd2(acc[q][c]);

        // attention postmix + ELU + store
        const float4* ap4 = (const float4*)(g_att + ((size_t)gl * NN + n) * 36);
        float at[36];
        #pragma unroll
        for (int k = 0; k < 9; ++k) {
            const float4 v = ap4[k];
            at[k * 4 + 0] = v.x; at[k * 4 + 1] = v.y;
            at[k * 4 + 2] = v.z; at[k * 4 + 3] = v.w;
        }

        float* ob = out + (((size_t)b * NN + n) * KH + gl * 6) * OD + cg * 4;
        #pragma unroll
        for (int p = 0; p < 6; ++p) {
            float o[4] = {0.f, 0.f, 0.f, 0.f};
            #pragma unroll
            for (int q = 0; q < 6; ++q) {
                const float aq = at[p * 6 + q];
                #pragma unroll
                for (int c = 0; c < 4; ++c)
                    o[c] = fmaf(aq, s[q][c], o[c]);
            }
            float4 o4;
            o4.x = o[0] > 0.f ? o[0] : expm1f(o[0]);
            o4.y = o[1] > 0.f ? o[1] : expm1f(o[1]);
            o4.z = o[2] > 0.f ? o[2] : expm1f(o[2]);
            o4.w = o[3] > 0.f ? o[3] : expm1f(o[3]);
            *(float4*)(ob + p * OD) = o4;
        }
    }
}

// ---------------------------------------------------------------------------
extern "C" void kernel_launch(void* const* d_in, const int* in_sizes, int n_in,
                              void* d_out, int out_size)
{
    (void)in_sizes; (void)n_in; (void)out_size;
    const float* h   = (const float*)d_in[0];
    const int*   adj = (const int*)d_in[1];
    const float* W   = (const float*)d_in[2];
    const float* a   = (const float*)d_in[3];
    float* out = (float*)d_out;

    attn_scores_kernel<<<1024, 128>>>(h, adj, W, a);
    gat_main_kernel<<<dim3(NN / 16, BATCH), THREADS>>>(h, W, out);
}

// round 6
// speedup vs baseline: 1.1353x; 1.1353x over previous
#include <cuda_runtime.h>
#include <cuda_pipeline.h>
#include <math.h>
#include <cstdint>

#define BATCH 16
#define NN    2048
#define KH    12
#define FD    128
#define OD    64

typedef unsigned int uint;

// ---------------- scratch (device globals; no allocation) ----------------
__device__ float g_att[2 * NN * 36];
__device__ float g_wa[512];           // [i][{a1,a2}][128]

// ---------------------------------------------------------------------------
// wa_kernel: g_wa[i][0/1][f] = sum_o W[f][o] * a[i][o or OF+o]
// ---------------------------------------------------------------------------
__global__ void wa_kernel(const float* __restrict__ W, const float* __restrict__ a)
{
    const int i = blockIdx.x;
    const int f = threadIdx.x;
    float r1 = 0.f, r2 = 0.f;
    const float* wr = W + f * OD;
    const float* ap = a + i * 2 * OD;
    #pragma unroll 16
    for (int o = 0; o < OD; ++o) {
        const float w = wr[o];
        r1 = fmaf(w, ap[o], r1);
        r2 = fmaf(w, ap[OD + o], r2);
    }
    g_wa[i * 256 + f]       = r1;
    g_wa[i * 256 + 128 + f] = r2;
}

// ---------------------------------------------------------------------------
// Kernel A: attention matrices. One warp per (i, n).
// ---------------------------------------------------------------------------
__global__ void __launch_bounds__(128) attn_scores_kernel(
    const float* __restrict__ h, const int* __restrict__ adj)
{
    __shared__ float wa1[FD], wa2[FD];
    const int t = threadIdx.x;
    const int i = blockIdx.x >> 9;

    wa1[t] = g_wa[i * 256 + t];
    wa2[t] = g_wa[i * 256 + 128 + t];
    __syncthreads();

    const int wid = t >> 5, l = t & 31;
    const int n = ((blockIdx.x & 511) << 2) + wid;

    float p1[6], p2[6];
    const float* hb = h + (((size_t)i * NN + n) * KH + i * 6) * FD;
    #pragma unroll
    for (int q = 0; q < 6; ++q) { p1[q] = 0.f; p2[q] = 0.f; }
    #pragma unroll
    for (int it = 0; it < 4; ++it) {
        const int f = l + it * 32;
        const float w1 = wa1[f], w2 = wa2[f];
        #pragma unroll
        for (int q = 0; q < 6; ++q) {
            const float hv = hb[q * FD + f];
            p1[q] = fmaf(hv, w1, p1[q]);
            p2[q] = fmaf(hv, w2, p2[q]);
        }
    }
    #pragma unroll
    for (int off = 16; off > 0; off >>= 1) {
        #pragma unroll
        for (int q = 0; q < 6; ++q) {
            p1[q] += __shfl_xor_sync(0xffffffffu, p1[q], off);
            p2[q] += __shfl_xor_sync(0xffffffffu, p2[q], off);
        }
    }

    if (l < 6) {
        const int p = l;
        float e[6];
        float m = -1e30f;
        #pragma unroll
        for (int q = 0; q < 6; ++q) {
            float v = p1[p] + p2[q];
            v = v > 0.f ? v : 0.2f * v;
            if (adj[i * 36 + p * 6 + q] <= 0) v = -9.0e15f;
            e[q] = v;
            m = fmaxf(m, v);
        }
        float sum = 0.f;
        #pragma unroll
        for (int q = 0; q < 6; ++q) { e[q] = expf(e[q] - m); sum += e[q]; }
        const float inv = 1.f / sum;
        float* dst = g_att + ((size_t)i * NN + n) * 36 + p * 6;
        #pragma unroll
        for (int q = 0; q < 6; ++q) dst[q] = e[q] * inv;
    }
}

// ---------------------------------------------------------------------------
// Main kernel: premix (attention before GEMM) + bf16 hi/lo mma.sync GEMM.
// Tile = 8 n = 96 rows x K128 x N64. 4 tiles per CTA. 256 threads.
// ---------------------------------------------------------------------------
#define SM_BHI  0                       // 64 x 64 words  = 16384 B
#define SM_BLO  16384
#define SM_AHI  32768                   // 96 rows x 256 B = 24576
#define SM_ALO  57344
#define SM_RAW  81920                   // 2 x 49152
#define SM_ATT  180224                  // 2 x 2304
#define SM_TOT  184832

__device__ __forceinline__ void split2(float v0, float v1, uint& hp, uint& lp) {
    asm("cvt.rn.bf16x2.f32 %0, %1, %2;" : "=r"(hp) : "f"(v1), "f"(v0));
    const float h0 = __uint_as_float(hp << 16);
    const float h1 = __uint_as_float(hp & 0xffff0000u);
    asm("cvt.rn.bf16x2.f32 %0, %1, %2;" : "=r"(lp) : "f"(v1 - h1), "f"(v0 - h0));
}
__device__ __forceinline__ uint smem_u32(const void* p) {
    uint a;
    asm("{ .reg .u64 t; cvta.to.shared.u64 t, %1; cvt.u32.u64 %0, t; }"
        : "=r"(a) : "l"(p));
    return a;
}
__device__ __forceinline__ void ldsm4(uint* r, uint addr) {
    asm volatile("ldmatrix.sync.aligned.m8n8.x4.shared.b16 {%0,%1,%2,%3}, [%4];"
                 : "=r"(r[0]), "=r"(r[1]), "=r"(r[2]), "=r"(r[3]) : "r"(addr));
}
__device__ __forceinline__ void mma16816(float* d, const uint* a, uint b0, uint b1) {
    asm volatile("mma.sync.aligned.m16n8k16.row.col.f32.bf16.bf16.f32 "
                 "{%0,%1,%2,%3}, {%4,%5,%6,%7}, {%8,%9}, {%0,%1,%2,%3};"
                 : "+f"(d[0]), "+f"(d[1]), "+f"(d[2]), "+f"(d[3])
                 : "r"(a[0]), "r"(a[1]), "r"(a[2]), "r"(a[3]), "r"(b0), "r"(b1));
}

__global__ void __launch_bounds__(256, 1) gat_main_kernel(
    const float* __restrict__ h, const float* __restrict__ W,
    float* __restrict__ out)
{
    extern __shared__ char smem[];
    const uint sb = smem_u32(smem);
    const int t = threadIdx.x;
    const int w = t >> 5;
    const int lane = t & 31;
    const int b = blockIdx.y;

    // ---- Bs setup: W -> transposed bf16 hi/lo, XOR-swizzled ----
    // Bs word (n, ww) = {W[2ww][n], W[2ww+1][n]} at index n*64 + (ww ^ 4*(n&7))
    {
        uint* BH = (uint*)(smem + SM_BHI);
        uint* BL = (uint*)(smem + SM_BLO);
        #pragma unroll
        for (int j = 0; j < 8; ++j) {
            const int ww = w * 8 + j;
            #pragma unroll
            for (int nh = 0; nh < 2; ++nh) {
                const int n = nh * 32 + lane;
                const float v0 = __ldg(W + (2 * ww) * OD + n);
                const float v1 = __ldg(W + (2 * ww + 1) * OD + n);
                uint hp, lp;
                split2(v0, v1, hp, lp);
                const int word = n * 64 + (ww ^ ((n & 7) << 2));
                BH[word] = hp;
                BL[word] = lp;
            }
        }
    }

    // ---- tile loader: raw h (49152 B contiguous) + att (8n x 72 floats) ----
    auto load_tile = [&](int tile, int buf) {
        const int n0 = tile * 8;
        const float4* src = (const float4*)
            (h + (((size_t)b * NN + n0) * KH) * FD);
        float4* dst = (float4*)(smem + SM_RAW + buf * 49152);
        #pragma unroll
        for (int i2 = 0; i2 < 12; ++i2)
            __pipeline_memcpy_async(dst + t + i2 * 256, src + t + i2 * 256, 16);
        if (t < 144) {
            const int nl = t / 18, rest = t - nl * 18;
            const int gi = rest / 9,  q4 = rest - gi * 9;
            __pipeline_memcpy_async(
                (float*)(smem + SM_ATT + buf * 2304) + nl * 72 + gi * 36 + q4 * 4,
                g_att + ((size_t)gi * NN + n0 + nl) * 36 + q4 * 4, 16);
        }
    };

    // ---- premix: Am[row][k] = sum_q att * raw, bf16 hi/lo into swizzled A ----
    auto premix = [&](int buf) {
        const float* rawb = (const float*)(smem + SM_RAW + buf * 49152);
        const float* attb = (const float*)(smem + SM_ATT + buf * 2304);
        #pragma unroll
        for (int it = 0; it < 6; ++it) {
            const int idx = t + it * 256;        // 0..1535
            const int row = idx >> 4;            // 0..95
            const int c   = idx & 15;            // 16B bf16 chunk (8 k)
            const int nl  = row / 12;
            const int kh  = row - nl * 12;
            const int gl  = kh / 6;
            const int p   = kh - gl * 6;
            const float* at = attb + nl * 72 + gl * 36 + p * 6;
            const float4* hr =
                (const float4*)(rawb + (nl * 12 + gl * 6) * FD) + c * 2;
            float a0 = 0.f, a1 = 0.f, a2 = 0.f, a3 = 0.f;
            float a4 = 0.f, a5 = 0.f, a6 = 0.f, a7 = 0.f;
            #pragma unroll
            for (int q = 0; q < 6; ++q) {
                const float aq = at[q];
                const float4 u = hr[q * 32];
                const float4 v = hr[q * 32 + 1];
                a0 = fmaf(aq, u.x, a0); a1 = fmaf(aq, u.y, a1);
                a2 = fmaf(aq, u.z, a2); a3 = fmaf(aq, u.w, a3);
                a4 = fmaf(aq, v.x, a4); a5 = fmaf(aq, v.y, a5);
                a6 = fmaf(aq, v.z, a6); a7 = fmaf(aq, v.w, a7);
            }
            uint4 hi4, lo4;
            split2(a0, a1, hi4.x, lo4.x);
            split2(a2, a3, hi4.y, lo4.y);
            split2(a4, a5, hi4.z, lo4.z);
            split2(a6, a7, hi4.w, lo4.w);
            const uint off = (uint)(row * 256 + ((c ^ (row & 7)) << 4));
            *(uint4*)(smem + SM_AHI + off) = hi4;
            *(uint4*)(smem + SM_ALO + off) = lo4;
        }
    };

    // per-lane geometry
    const int g     = lane >> 3;
    const int arow  = ((g & 1) << 3) + (lane & 7);   // row within m16 tile
    const int acoff = g >> 1;                        // k 16B-subblock 0/1
    const int as7   = arow & 7;
    const int nB    = w * 8 + (lane >> 2);           // global output col tile row
    const int bxm   = (nB & 7) << 2;
    const int bw0   = lane & 3;
    const uint* BH  = (const uint*)(smem + SM_BHI);
    const uint* BL  = (const uint*)(smem + SM_BLO);
    const int r0l   = lane >> 2;
    const int c0    = w * 8 + (lane & 3) * 2;

    const int tile0 = blockIdx.x * 4;
    load_tile(tile0, 0);
    __pipeline_commit();

    for (int tl = 0; tl < 4; ++tl) {
        const int buf = tl & 1;
        __pipeline_wait_prior(0);
        __syncthreads();                 // raw ready; A free (prev mma done)

        premix(buf);
        __syncthreads();

        if (tl < 3) { load_tile(tile0 + tl + 1, buf ^ 1); __pipeline_commit(); }

        // ---- GEMM: warp w -> col tile w (8 cols), all 6 row tiles ----
        float d[6][4];
        #pragma unroll
        for (int rt = 0; rt < 6; ++rt)
            #pragma unroll
            for (int e = 0; e < 4; ++e) d[rt][e] = 0.f;

        #pragma unroll 2
        for (int s = 0; s < 8; ++s) {
            const uint bh0 = BH[nB * 64 + ((bw0 + 8 * s) ^ bxm)];
            const uint bh1 = BH[nB * 64 + ((bw0 + 4 + 8 * s) ^ bxm)];
            const uint bl0 = BL[nB * 64 + ((bw0 + 8 * s) ^ bxm)];
            const uint bl1 = BL[nB * 64 + ((bw0 + 4 + 8 * s) ^ bxm)];
            #pragma unroll
            for (int rt = 0; rt < 6; ++rt) {
                const uint ra = (uint)((rt * 16 + arow) * 256
                                       + (((2 * s + acoff) ^ as7) << 4));
                uint ah[4], al[4];
                ldsm4(ah, sb + SM_AHI + ra);
                ldsm4(al, sb + SM_ALO + ra);
                mma16816(d[rt], ah, bh0, bh1);
                mma16816(d[rt], ah, bl0, bl1);
                mma16816(d[rt], al, bh0, bh1);
            }
        }

        // ---- epilogue: ELU + store ----
        const int n0 = tile0 * 8 + tl * 8;
        #pragma unroll
        for (int rt = 0; rt < 6; ++rt) {
            #pragma unroll
            for (int hf = 0; hf < 2; ++hf) {
                const int row = rt * 16 + r0l + hf * 8;
                const int nl  = row / 12;
                const int kh  = row - nl * 12;
                const float e0r = d[rt][hf * 2];
                const float e1r = d[rt][hf * 2 + 1];
                float2 o;
                o.x = e0r > 0.f ? e0r : expm1f(e0r);
                o.y = e1r > 0.f ? e1r : expm1f(e1r);
                *(float2*)(out + (((size_t)b * NN + n0 + nl) * KH + kh) * OD
                           + c0) = o;
            }
        }
        __syncthreads();   // A planes reusable next iter
    }
}

// ---------------------------------------------------------------------------
extern "C" void kernel_launch(void* const* d_in, const int* in_sizes, int n_in,
                              void* d_out, int out_size)
{
    (void)in_sizes; (void)n_in; (void)out_size;
    const float* h   = (const float*)d_in[0];
    const int*   adj = (const int*)d_in[1];
    const float* W   = (const float*)d_in[2];
    const float* a   = (const float*)d_in[3];
    float* out = (float*)d_out;

    wa_kernel<<<2, 128>>>(W, a);
    attn_scores_kernel<<<1024, 128>>>(h, adj);

    cudaFuncSetAttribute(gat_main_kernel,
                         cudaFuncAttributeMaxDynamicSharedMemorySize, SM_TOT);
    gat_main_kernel<<<dim3(64, BATCH), 256, SM_TOT>>>(h, W, out);
}

// round 7
// speedup vs baseline: 1.5336x; 1.3509x over previous
#include <cuda_runtime.h>
#include <math.h>
#include <cstdint>

#define BATCH 16
#define NN    2048
#define KH    12
#define FD    128
#define OD    64

typedef unsigned int uint;

// ---------------- scratch (device global; no allocation) ----------------
__device__ float g_att[2 * NN * 36];

// ---------------------------------------------------------------------------
// Kernel A: attention matrices. One warp per (i, n); W@a inlined.
// ---------------------------------------------------------------------------
__global__ void __launch_bounds__(128) attn_scores_kernel(
    const float* __restrict__ h, const int* __restrict__ adj,
    const float* __restrict__ W, const float* __restrict__ a)
{
    __shared__ float wa1[FD], wa2[FD];
    const int t = threadIdx.x;
    const int i = blockIdx.x >> 9;               // 1024 blocks: 512 per i

    {   // wa = W @ a1 / a2 (one f per thread)
        float r1 = 0.f, r2 = 0.f;
        const float* wr = W + t * OD;
        const float* ap = a + i * 2 * OD;
        #pragma unroll 16
        for (int o = 0; o < OD; ++o) {
            const float w = wr[o];
            r1 = fmaf(w, ap[o], r1);
            r2 = fmaf(w, ap[OD + o], r2);
        }
        wa1[t] = r1; wa2[t] = r2;
    }
    __syncthreads();

    const int wid = t >> 5, l = t & 31;
    const int n = ((blockIdx.x & 511) << 2) + wid;

    float p1[6], p2[6];
    const float* hb = h + (((size_t)i * NN + n) * KH + i * 6) * FD;
    #pragma unroll
    for (int q = 0; q < 6; ++q) { p1[q] = 0.f; p2[q] = 0.f; }
    #pragma unroll
    for (int it = 0; it < 4; ++it) {
        const int f = l + it * 32;
        const float w1 = wa1[f], w2 = wa2[f];
        #pragma unroll
        for (int q = 0; q < 6; ++q) {
            const float hv = hb[q * FD + f];
            p1[q] = fmaf(hv, w1, p1[q]);
            p2[q] = fmaf(hv, w2, p2[q]);
        }
    }
    #pragma unroll
    for (int off = 16; off > 0; off >>= 1) {
        #pragma unroll
        for (int q = 0; q < 6; ++q) {
            p1[q] += __shfl_xor_sync(0xffffffffu, p1[q], off);
            p2[q] += __shfl_xor_sync(0xffffffffu, p2[q], off);
        }
    }

    if (l < 6) {
        const int p = l;
        float e[6];
        float m = -1e30f;
        #pragma unroll
        for (int q = 0; q < 6; ++q) {
            float v = p1[p] + p2[q];
            v = v > 0.f ? v : 0.2f * v;
            if (adj[i * 36 + p * 6 + q] <= 0) v = -9.0e15f;
            e[q] = v;
            m = fmaxf(m, v);
        }
        float sum = 0.f;
        #pragma unroll
        for (int q = 0; q < 6; ++q) { e[q] = expf(e[q] - m); sum += e[q]; }
        const float inv = 1.f / sum;
        float* dst = g_att + ((size_t)i * NN + n) * 36 + p * 6;
        #pragma unroll
        for (int q = 0; q < 6; ++q) dst[q] = e[q] * inv;
    }
}

// ---------------------------------------------------------------------------
// Main kernel: premix-from-gmem (coalesced LDG) + bf16 hi/lo mma.sync GEMM.
// Tile = 8 n = 96 rows x K128 x N64. 4 tiles per CTA. 256 threads, 2 CTA/SM.
// ---------------------------------------------------------------------------
#define SM_BHI  0                       // 64 x 64 words  = 16384 B
#define SM_BLO  16384
#define SM_AHI  32768                   // 96 rows x 256 B = 24576
#define SM_ALO  57344
#define SM_TOT  81920

__device__ __forceinline__ void split2(float v0, float v1, uint& hp, uint& lp) {
    asm("cvt.rn.bf16x2.f32 %0, %1, %2;" : "=r"(hp) : "f"(v1), "f"(v0));
    const float h0 = __uint_as_float(hp << 16);
    const float h1 = __uint_as_float(hp & 0xffff0000u);
    asm("cvt.rn.bf16x2.f32 %0, %1, %2;" : "=r"(lp) : "f"(v1 - h1), "f"(v0 - h0));
}
__device__ __forceinline__ uint smem_u32(const void* p) {
    uint a;
    asm("{ .reg .u64 t; cvta.to.shared.u64 t, %1; cvt.u32.u64 %0, t; }"
        : "=r"(a) : "l"(p));
    return a;
}
__device__ __forceinline__ void ldsm4(uint* r, uint addr) {
    asm volatile("ldmatrix.sync.aligned.m8n8.x4.shared.b16 {%0,%1,%2,%3}, [%4];"
                 : "=r"(r[0]), "=r"(r[1]), "=r"(r[2]), "=r"(r[3]) : "r"(addr));
}
__device__ __forceinline__ void mma16816(float* d, const uint* a, uint b0, uint b1) {
    asm volatile("mma.sync.aligned.m16n8k16.row.col.f32.bf16.bf16.f32 "
                 "{%0,%1,%2,%3}, {%4,%5,%6,%7}, {%8,%9}, {%0,%1,%2,%3};"
                 : "+f"(d[0]), "+f"(d[1]), "+f"(d[2]), "+f"(d[3])
                 : "r"(a[0]), "r"(a[1]), "r"(a[2]), "r"(a[3]), "r"(b0), "r"(b1));
}

__global__ void __launch_bounds__(256, 2) gat_main_kernel(
    const float* __restrict__ h, const float* __restrict__ W,
    float* __restrict__ out)
{
    extern __shared__ char smem[];
    const uint sb = smem_u32(smem);
    const int t = threadIdx.x;
    const int w = t >> 5;
    const int lane = t & 31;
    const int b = blockIdx.y;

    // ---- Bs setup: W -> transposed bf16 hi/lo, XOR-swizzled ----
    {
        uint* BH = (uint*)(smem + SM_BHI);
        uint* BL = (uint*)(smem + SM_BLO);
        #pragma unroll
        for (int j = 0; j < 8; ++j) {
            const int ww = w * 8 + j;
            #pragma unroll
            for (int nh = 0; nh < 2; ++nh) {
                const int n = nh * 32 + lane;
                const float v0 = __ldg(W + (2 * ww) * OD + n);
                const float v1 = __ldg(W + (2 * ww + 1) * OD + n);
                uint hp, lp;
                split2(v0, v1, hp, lp);
                const int word = n * 64 + (ww ^ ((n & 7) << 2));
                BH[word] = hp;
                BL[word] = lp;
            }
        }
    }

    // per-lane GEMM geometry (identical to verified round-6 kernel)
    const int g     = lane >> 3;
    const int arow  = ((g & 1) << 3) + (lane & 7);
    const int acoff = g >> 1;
    const int as7   = arow & 7;
    const int nB    = w * 8 + (lane >> 2);
    const int bxm   = (nB & 7) << 2;
    const int bw0   = lane & 3;
    const uint* BH  = (const uint*)(smem + SM_BHI);
    const uint* BL  = (const uint*)(smem + SM_BLO);
    const int r0l   = lane >> 2;
    const int c0    = w * 8 + (lane & 3) * 2;

    const int tile0 = blockIdx.x * 4;

    for (int tl = 0; tl < 4; ++tl) {
        const int n0 = (tile0 + tl) * 8;

        // ---- premix: warp-jobs (nl, gl); LDG h rows, mix by att, split ----
        #pragma unroll
        for (int jj = 0; jj < 2; ++jj) {
            const int job = w + jj * 8;           // 0..15
            const int nl  = job >> 1;
            const int gl  = job & 1;
            const int n   = n0 + nl;

            const float* hrow = h + (((size_t)b * NN + n) * KH + gl * 6) * FD
                                  + lane * 4;
            float4 hq[6];
            #pragma unroll
            for (int q = 0; q < 6; ++q)
                hq[q] = *(const float4*)(hrow + q * FD);

            float at[36];
            const float4* ap4 =
                (const float4*)(g_att + ((size_t)gl * NN + n) * 36);
            #pragma unroll
            for (int k = 0; k < 9; ++k) {
                const float4 v = __ldg(ap4 + k);
                at[k * 4 + 0] = v.x; at[k * 4 + 1] = v.y;
                at[k * 4 + 2] = v.z; at[k * 4 + 3] = v.w;
            }

            const int rbase = nl * 12 + gl * 6;
            const int c     = lane >> 1;          // 16B chunk 0..15
            const int half8 = (lane & 1) * 8;
            #pragma unroll
            for (int p = 0; p < 6; ++p) {
                float a0 = 0.f, a1 = 0.f, a2 = 0.f, a3 = 0.f;
                #pragma unroll
                for (int q = 0; q < 6; ++q) {
                    const float aq = at[p * 6 + q];
                    a0 = fmaf(aq, hq[q].x, a0);
                    a1 = fmaf(aq, hq[q].y, a1);
                    a2 = fmaf(aq, hq[q].z, a2);
                    a3 = fmaf(aq, hq[q].w, a3);
                }
                uint h0, l0, h1, l1;
                split2(a0, a1, h0, l0);
                split2(a2, a3, h1, l1);
                const int r = rbase + p;
                const uint off = (uint)(r * 256 + (((c ^ (r & 7))) << 4) + half8);
                *(uint2*)(smem + SM_AHI + off) = make_uint2(h0, h1);
                *(uint2*)(smem + SM_ALO + off) = make_uint2(l0, l1);
            }
        }
        __syncthreads();

        // ---- GEMM: warp w -> col tile w (8 cols), all 6 row tiles ----
        float d[6][4];
        #pragma unroll
        for (int rt = 0; rt < 6; ++rt)
            #pragma unroll
            for (int e = 0; e < 4; ++e) d[rt][e] = 0.f;

        #pragma unroll 2
        for (int s = 0; s < 8; ++s) {
            const uint bh0 = BH[nB * 64 + ((bw0 + 8 * s) ^ bxm)];
            const uint bh1 = BH[nB * 64 + ((bw0 + 4 + 8 * s) ^ bxm)];
            const uint bl0 = BL[nB * 64 + ((bw0 + 8 * s) ^ bxm)];
            const uint bl1 = BL[nB * 64 + ((bw0 + 4 + 8 * s) ^ bxm)];
            #pragma unroll
            for (int rt = 0; rt < 6; ++rt) {
                const uint ra = (uint)((rt * 16 + arow) * 256
                                       + (((2 * s + acoff) ^ as7) << 4));
                uint ah[4], al[4];
                ldsm4(ah, sb + SM_AHI + ra);
                ldsm4(al, sb + SM_ALO + ra);
                mma16816(d[rt], ah, bh0, bh1);
                mma16816(d[rt], ah, bl0, bl1);
                mma16816(d[rt], al, bh0, bh1);
            }
        }

        // ---- epilogue: ELU + store ----
        #pragma unroll
        for (int rt = 0; rt < 6; ++rt) {
            #pragma unroll
            for (int hf = 0; hf < 2; ++hf) {
                const int row = rt * 16 + r0l + hf * 8;
                const int nl  = row / 12;
                const int kh  = row - nl * 12;
                const float e0r = d[rt][hf * 2];
                const float e1r = d[rt][hf * 2 + 1];
                float2 o;
                o.x = e0r > 0.f ? e0r : expm1f(e0r);
                o.y = e1r > 0.f ? e1r : expm1f(e1r);
                *(float2*)(out + (((size_t)b * NN + n0 + nl) * KH + kh) * OD
                           + c0) = o;
            }
        }
        __syncthreads();   // A planes reusable next tile
    }
}

// ---------------------------------------------------------------------------
extern "C" void kernel_launch(void* const* d_in, const int* in_sizes, int n_in,
                              void* d_out, int out_size)
{
    (void)in_sizes; (void)n_in; (void)out_size;
    const float* h   = (const float*)d_in[0];
    const int*   adj = (const int*)d_in[1];
    const float* W   = (const float*)d_in[2];
    const float* a   = (const float*)d_in[3];
    float* out = (float*)d_out;

    attn_scores_kernel<<<1024, 128>>>(h, adj, W, a);

    cudaFuncSetAttribute(gat_main_kernel,
                         cudaFuncAttributeMaxDynamicSharedMemorySize, SM_TOT);
    gat_main_kernel<<<dim3(64, BATCH), 256, SM_TOT>>>(h, W, out);
}

// round 8
// speedup vs baseline: 1.7138x; 1.1175x over previous
#include <cuda_runtime.h>
#include <math.h>
#include <cstdint>

#define BATCH 16
#define NN    2048
#define KH    12
#define FD    128
#define OD    64

typedef unsigned int uint;

// ---------------- scratch (device global; no allocation) ----------------
__device__ float g_att[2 * NN * 36];

// ---------------------------------------------------------------------------
// Kernel A: attention matrices. One warp per (i, n); W@a inlined.
// 512 blocks x 256 threads; lane owns f = 4l..4l+3 (float4 loads).
// ---------------------------------------------------------------------------
__global__ void __launch_bounds__(256) attn_scores_kernel(
    const float* __restrict__ h, const int* __restrict__ adj,
    const float* __restrict__ W, const float* __restrict__ a)
{
    __shared__ float wa1[FD], wa2[FD];
    const int t = threadIdx.x;
    const int i = blockIdx.x >> 8;               // 512 blocks: 256 per i

    if (t < FD) {   // wa = W @ a1 / a2 (one f per thread)
        float r1 = 0.f, r2 = 0.f;
        const float* wr = W + t * OD;
        const float* ap = a + i * 2 * OD;
        #pragma unroll 16
        for (int o = 0; o < OD; ++o) {
            const float w = wr[o];
            r1 = fmaf(w, ap[o], r1);
            r2 = fmaf(w, ap[OD + o], r2);
        }
        wa1[t] = r1; wa2[t] = r2;
    }
    __syncthreads();

    const int wid = t >> 5, l = t & 31;
    const int n = ((blockIdx.x & 255) << 3) + wid;

    const float4 w1 = *(const float4*)(wa1 + 4 * l);
    const float4 w2 = *(const float4*)(wa2 + 4 * l);

    float p1[6], p2[6];
    const float* hb = h + (((size_t)i * NN + n) * KH + i * 6) * FD + 4 * l;
    #pragma unroll
    for (int q = 0; q < 6; ++q) {
        const float4 hv = *(const float4*)(hb + q * FD);
        p1[q] = hv.x * w1.x + hv.y * w1.y + hv.z * w1.z + hv.w * w1.w;
        p2[q] = hv.x * w2.x + hv.y * w2.y + hv.z * w2.z + hv.w * w2.w;
    }
    #pragma unroll
    for (int off = 16; off > 0; off >>= 1) {
        #pragma unroll
        for (int q = 0; q < 6; ++q) {
            p1[q] += __shfl_xor_sync(0xffffffffu, p1[q], off);
            p2[q] += __shfl_xor_sync(0xffffffffu, p2[q], off);
        }
    }

    if (l < 6) {
        const int p = l;
        float e[6];
        float m = -1e30f;
        #pragma unroll
        for (int q = 0; q < 6; ++q) {
            float v = p1[p] + p2[q];
            v = v > 0.f ? v : 0.2f * v;
            if (adj[i * 36 + p * 6 + q] <= 0) v = -9.0e15f;
            e[q] = v;
            m = fmaxf(m, v);
        }
        float sum = 0.f;
        #pragma unroll
        for (int q = 0; q < 6; ++q) { e[q] = expf(e[q] - m); sum += e[q]; }
        const float inv = 1.f / sum;
        float* dst = g_att + ((size_t)i * NN + n) * 36 + p * 6;
        #pragma unroll
        for (int q = 0; q < 6; ++q) dst[q] = e[q] * inv;
    }
}

// ---------------------------------------------------------------------------
// Main kernel: premix-from-gmem + bf16 hi/lo mma.sync GEMM.
// Tile = 8 n = 96 rows x K128 x N64. 4 tiles per CTA. 256 threads, 2 CTA/SM.
// Warp = 3 row-tiles x 16 cols (A-ldsm amortized over 2 col-tiles).
// ---------------------------------------------------------------------------
#define SM_BHI  0                       // 64 x 64 words  = 16384 B
#define SM_BLO  16384
#define SM_AHI  32768                   // 96 rows x 256 B = 24576
#define SM_ALO  57344
#define SM_TOT  81920

__device__ __forceinline__ void split2(float v0, float v1, uint& hp, uint& lp) {
    asm("cvt.rn.bf16x2.f32 %0, %1, %2;" : "=r"(hp) : "f"(v1), "f"(v0));
    const float h0 = __uint_as_float(hp << 16);
    const float h1 = __uint_as_float(hp & 0xffff0000u);
    asm("cvt.rn.bf16x2.f32 %0, %1, %2;" : "=r"(lp) : "f"(v1 - h1), "f"(v0 - h0));
}
__device__ __forceinline__ uint smem_u32(const void* p) {
    uint a;
    asm("{ .reg .u64 t; cvta.to.shared.u64 t, %1; cvt.u32.u64 %0, t; }"
        : "=r"(a) : "l"(p));
    return a;
}
__device__ __forceinline__ void ldsm4(uint* r, uint addr) {
    asm volatile("ldmatrix.sync.aligned.m8n8.x4.shared.b16 {%0,%1,%2,%3}, [%4];"
                 : "=r"(r[0]), "=r"(r[1]), "=r"(r[2]), "=r"(r[3]) : "r"(addr));
}
__device__ __forceinline__ void mma16816(float* d, const uint* a, uint b0, uint b1) {
    asm volatile("mma.sync.aligned.m16n8k16.row.col.f32.bf16.bf16.f32 "
                 "{%0,%1,%2,%3}, {%4,%5,%6,%7}, {%8,%9}, {%0,%1,%2,%3};"
                 : "+f"(d[0]), "+f"(d[1]), "+f"(d[2]), "+f"(d[3])
                 : "r"(a[0]), "r"(a[1]), "r"(a[2]), "r"(a[3]), "r"(b0), "r"(b1));
}

__global__ void __launch_bounds__(256, 2) gat_main_kernel(
    const float* __restrict__ h, const float* __restrict__ W,
    float* __restrict__ out)
{
    extern __shared__ char smem[];
    const uint sb = smem_u32(smem);
    const int t = threadIdx.x;
    const int w = t >> 5;
    const int lane = t & 31;
    const int b = blockIdx.y;

    // ---- Bs setup: W -> transposed bf16 hi/lo, XOR-swizzled ----
    {
        uint* BH = (uint*)(smem + SM_BHI);
        uint* BL = (uint*)(smem + SM_BLO);
        #pragma unroll
        for (int j = 0; j < 8; ++j) {
            const int ww = w * 8 + j;
            #pragma unroll
            for (int nh = 0; nh < 2; ++nh) {
                const int n = nh * 32 + lane;
                const float v0 = __ldg(W + (2 * ww) * OD + n);
                const float v1 = __ldg(W + (2 * ww + 1) * OD + n);
                uint hp, lp;
                split2(v0, v1, hp, lp);
                const int word = n * 64 + (ww ^ ((n & 7) << 2));
                BH[word] = hp;
                BL[word] = lp;
            }
        }
    }

    // per-lane GEMM geometry: warp -> (rw = row half, wc = 16-col block)
    const int wc    = w & 3;
    const int rw    = w >> 2;
    const int g     = lane >> 3;
    const int arow  = ((g & 1) << 3) + (lane & 7);
    const int acoff = g >> 1;
    const int as7   = arow & 7;
    const int nB0   = wc * 16 + (lane >> 2);       // col-tile 0 row in Bs
    const int nB1   = nB0 + 8;                     // col-tile 1
    const int bxm0  = (nB0 & 7) << 2;              // same for nB1 (bit3 differs)
    const int bw0   = lane & 3;
    const uint* BH  = (const uint*)(smem + SM_BHI);
    const uint* BL  = (const uint*)(smem + SM_BLO);
    const int r0l   = lane >> 2;
    const int c0b   = wc * 16 + (lane & 3) * 2;

    const int tile0 = blockIdx.x * 4;

    for (int tl = 0; tl < 4; ++tl) {
        const int n0 = (tile0 + tl) * 8;

        // ---- premix: warp-jobs (nl, gl); LDG h rows, mix by att, split ----
        #pragma unroll
        for (int jj = 0; jj < 2; ++jj) {
            const int job = w + jj * 8;           // 0..15
            const int nl  = job >> 1;
            const int gl  = job & 1;
            const int n   = n0 + nl;

            const float* hrow = h + (((size_t)b * NN + n) * KH + gl * 6) * FD
                                  + lane * 4;
            float4 hq[6];
            #pragma unroll
            for (int q = 0; q < 6; ++q)
                hq[q] = *(const float4*)(hrow + q * FD);

            float at[36];
            const float4* ap4 =
                (const float4*)(g_att + ((size_t)gl * NN + n) * 36);
            #pragma unroll
            for (int k = 0; k < 9; ++k) {
                const float4 v = __ldg(ap4 + k);
                at[k * 4 + 0] = v.x; at[k * 4 + 1] = v.y;
                at[k * 4 + 2] = v.z; at[k * 4 + 3] = v.w;
            }

            const int rbase = nl * 12 + gl * 6;
            const int c     = lane >> 1;          // 16B chunk 0..15
            const int half8 = (lane & 1) * 8;
            #pragma unroll
            for (int p = 0; p < 6; ++p) {
                float a0 = 0.f, a1 = 0.f, a2 = 0.f, a3 = 0.f;
                #pragma unroll
                for (int q = 0; q < 6; ++q) {
                    const float aq = at[p * 6 + q];
                    a0 = fmaf(aq, hq[q].x, a0);
                    a1 = fmaf(aq, hq[q].y, a1);
                    a2 = fmaf(aq, hq[q].z, a2);
                    a3 = fmaf(aq, hq[q].w, a3);
                }
                uint h0, l0, h1, l1;
                split2(a0, a1, h0, l0);
                split2(a2, a3, h1, l1);
                const int r = rbase + p;
                const uint off = (uint)(r * 256 + (((c ^ (r & 7))) << 4) + half8);
                *(uint2*)(smem + SM_AHI + off) = make_uint2(h0, h1);
                *(uint2*)(smem + SM_ALO + off) = make_uint2(l0, l1);
            }
        }
        __syncthreads();

        // ---- GEMM: warp -> rows rw*48..+47 (3 m16 tiles), 16 cols ----
        float d[3][2][4];
        #pragma unroll
        for (int rti = 0; rti < 3; ++rti)
            #pragma unroll
            for (int ct = 0; ct < 2; ++ct)
                #pragma unroll
                for (int e = 0; e < 4; ++e) d[rti][ct][e] = 0.f;

        #pragma unroll 2
        for (int s = 0; s < 8; ++s) {
            const int i0 = (bw0 + 8 * s) ^ bxm0;
            const int i1 = (bw0 + 4 + 8 * s) ^ bxm0;
            const uint bh0[2] = { BH[nB0 * 64 + i0], BH[nB1 * 64 + i0] };
            const uint bh1[2] = { BH[nB0 * 64 + i1], BH[nB1 * 64 + i1] };
            const uint bl0[2] = { BL[nB0 * 64 + i0], BL[nB1 * 64 + i0] };
            const uint bl1[2] = { BL[nB0 * 64 + i1], BL[nB1 * 64 + i1] };
            #pragma unroll
            for (int rti = 0; rti < 3; ++rti) {
                const int rt = rw * 3 + rti;
                const uint ra = (uint)((rt * 16 + arow) * 256
                                       + (((2 * s + acoff) ^ as7) << 4));
                uint ah[4], al[4];
                ldsm4(ah, sb + SM_AHI + ra);
                ldsm4(al, sb + SM_ALO + ra);
                #pragma unroll
                for (int ct = 0; ct < 2; ++ct) {
                    mma16816(d[rti][ct], ah, bh0[ct], bh1[ct]);
                    mma16816(d[rti][ct], ah, bl0[ct], bl1[ct]);
                    mma16816(d[rti][ct], al, bh0[ct], bh1[ct]);
                }
            }
        }

        // ---- epilogue: ELU + store ----
        #pragma unroll
        for (int rti = 0; rti < 3; ++rti) {
            #pragma unroll
            for (int hf = 0; hf < 2; ++hf) {
                const int row = (rw * 3 + rti) * 16 + r0l + hf * 8;
                const int nl  = row / 12;
                const int kh  = row - nl * 12;
                float* ob = out + (((size_t)b * NN + n0 + nl) * KH + kh) * OD;
                #pragma unroll
                for (int ct = 0; ct < 2; ++ct) {
                    const float e0r = d[rti][ct][hf * 2];
                    const float e1r = d[rti][ct][hf * 2 + 1];
                    float2 o;
                    o.x = e0r > 0.f ? e0r : expm1f(e0r);
                    o.y = e1r > 0.f ? e1r : expm1f(e1r);
                    *(float2*)(ob + c0b + ct * 8) = o;
                }
            }
        }
        __syncthreads();   // A planes reusable next tile
    }
}

// ---------------------------------------------------------------------------
extern "C" void kernel_launch(void* const* d_in, const int* in_sizes, int n_in,
                              void* d_out, int out_size)
{
    (void)in_sizes; (void)n_in; (void)out_size;
    const float* h   = (const float*)d_in[0];
    const int*   adj = (const int*)d_in[1];
    const float* W   = (const float*)d_in[2];
    const float* a   = (const float*)d_in[3];
    float* out = (float*)d_out;

    attn_scores_kernel<<<512, 256>>>(h, adj, W, a);

    cudaFuncSetAttribute(gat_main_kernel,
                         cudaFuncAttributeMaxDynamicSharedMemorySize, SM_TOT);
    gat_main_kernel<<<dim3(64, BATCH), 256, SM_TOT>>>(h, W, out);
}